// round 2
// baseline (speedup 1.0000x reference)
#include <cuda_runtime.h>
#include <math.h>

#define BSZ 4096
#define DDIM 512
#define N2 8192
#define TILE 64
#define TK 16
#define APAD 68   // 68*4 bytes row stride: 16B-aligned rows + reduced bank conflicts

// Scratch (device globals; no allocation in kernel_launch)
__device__ float g_reps[(size_t)N2 * DDIM];   // 16 MB, L2-resident
__device__ int   g_labels[N2];
__device__ float g_denom[N2];
__device__ float g_pos[N2];

// ---------------------------------------------------------------------------
// Kernel 0: decode labels, robust to target being int32 OR int64 (LE).
// If the buffer is int64, the odd int32 words of the first 4096 ints are all
// zero high-words (values in [0,100)); if int32 targets, they're random
// nonzero with overwhelming probability. Reads <= 16KB: safe either way.
// ---------------------------------------------------------------------------
__global__ void labels_kernel(const int* __restrict__ traw) {
    __shared__ int odd_nonzero;
    if (threadIdx.x == 0) odd_nonzero = 0;
    __syncthreads();
    int local = 0;
    for (int i = threadIdx.x; i < BSZ / 2; i += 256)
        if (traw[2 * i + 1] != 0) local = 1;
    if (local) atomicOr(&odd_nonzero, 1);
    __syncthreads();
    const bool is64 = (odd_nonzero == 0);
    for (int i = threadIdx.x; i < BSZ; i += 256) {
        int v = is64 ? traw[2 * i] : traw[i];
        g_labels[i] = v;
        g_labels[i + BSZ] = v;
    }
}

// ---------------------------------------------------------------------------
// Kernel 1: L2-normalize rows of [emb_i; emb_j] into g_reps
// ---------------------------------------------------------------------------
__global__ void normalize_kernel(const float* __restrict__ emb_i,
                                 const float* __restrict__ emb_j) {
    int row = blockIdx.x;                  // 0..8191
    const float* src = (row < BSZ) ? (emb_i + (size_t)row * DDIM)
                                   : (emb_j + (size_t)(row - BSZ) * DDIM);
    int t = threadIdx.x;                   // 128 threads, 4 floats each
    float4 v = reinterpret_cast<const float4*>(src)[t];
    float ss = v.x * v.x + v.y * v.y + v.z * v.z + v.w * v.w;
#pragma unroll
    for (int o = 16; o; o >>= 1) ss += __shfl_xor_sync(0xffffffffu, ss, o);
    __shared__ float ws[4];
    if ((t & 31) == 0) ws[t >> 5] = ss;
    __syncthreads();
    float tot = ws[0] + ws[1] + ws[2] + ws[3];
    float inv = 1.0f / fmaxf(sqrtf(tot), 1e-12f);
    float4 o4 = make_float4(v.x * inv, v.y * inv, v.z * inv, v.w * inv);
    reinterpret_cast<float4*>(g_reps + (size_t)row * DDIM)[t] = o4;
}

// ---------------------------------------------------------------------------
// Kernel 2: fused sim-tile GEMM + mask + exp + row-sum.
// Grid = N2/TILE = 128 blocks; block b owns rows [b*64, b*64+64) and loops
// over all 128 column tiles. 256 threads as 16x16, 4x4 micro-tile each.
// ---------------------------------------------------------------------------
__global__ void __launch_bounds__(256) simloss_kernel() {
    __shared__ __align__(16) float As[TK][APAD];
    __shared__ __align__(16) float Bs[TK][APAD];
    __shared__ int   li_s[TILE];
    __shared__ int   lj_s[TILE];
    __shared__ float red[TILE][16];

    const int tid = threadIdx.x;
    const int tx = tid & 15;
    const int ty = tid >> 4;
    const int iBase = blockIdx.x * TILE;

    if (tid < TILE) li_s[tid] = g_labels[iBase + tid];

    // loader mapping: 256 threads load a 64x16 tile as float4s
    const int lrow = tid >> 2;         // 0..63
    const int lk4  = (tid & 3) * 4;    // 0,4,8,12

    float rowsum[4] = {0.f, 0.f, 0.f, 0.f};

    for (int jBase = 0; jBase < N2; jBase += TILE) {
        if (tid < TILE) lj_s[tid] = g_labels[jBase + tid];

        float acc[4][4] = {};

        for (int kc = 0; kc < DDIM; kc += TK) {
            float4 a = *reinterpret_cast<const float4*>(
                g_reps + (size_t)(iBase + lrow) * DDIM + kc + lk4);
            float4 b = *reinterpret_cast<const float4*>(
                g_reps + (size_t)(jBase + lrow) * DDIM + kc + lk4);
            __syncthreads();   // previous chunk's reads done
            As[lk4 + 0][lrow] = a.x; As[lk4 + 1][lrow] = a.y;
            As[lk4 + 2][lrow] = a.z; As[lk4 + 3][lrow] = a.w;
            Bs[lk4 + 0][lrow] = b.x; Bs[lk4 + 1][lrow] = b.y;
            Bs[lk4 + 2][lrow] = b.z; Bs[lk4 + 3][lrow] = b.w;
            __syncthreads();
#pragma unroll
            for (int k = 0; k < TK; ++k) {
                float4 av = *reinterpret_cast<const float4*>(&As[k][ty * 4]);
                float4 bv = *reinterpret_cast<const float4*>(&Bs[k][tx * 4]);
                float ar[4] = {av.x, av.y, av.z, av.w};
                float br[4] = {bv.x, bv.y, bv.z, bv.w};
#pragma unroll
                for (int r = 0; r < 4; ++r)
#pragma unroll
                    for (int c = 0; c < 4; ++c)
                        acc[r][c] = fmaf(ar[r], br[c], acc[r][c]);
            }
        }

        // epilogue: mask + exp, accumulate row sums; record positives
#pragma unroll
        for (int r = 0; r < 4; ++r) {
            int gi = iBase + ty * 4 + r;
            int li = li_s[ty * 4 + r];
#pragma unroll
            for (int c = 0; c < 4; ++c) {
                int gj = jBase + tx * 4 + c;
                float s = acc[r][c];
                int d = gi - gj;
                bool is_pos = (d == BSZ) || (d == -BSZ);
                if (is_pos) g_pos[gi] = s;   // exactly one writer per row
                bool excl = (gi == gj) || ((li == lj_s[tx * 4 + c]) && !is_pos);
                if (!excl) rowsum[r] += expf(2.0f * s);  // 1/TEMPERATURE = 2
            }
        }
        __syncthreads();   // protect lj_s before next tile overwrites it
    }

    // cross-thread row-sum reduction (16 partials per row)
#pragma unroll
    for (int r = 0; r < 4; ++r) red[ty * 4 + r][tx] = rowsum[r];
    __syncthreads();
    if (tid < TILE) {
        float s = 0.f;
#pragma unroll
        for (int c = 0; c < 16; ++c) s += red[tid][c];
        g_denom[iBase + tid] = s;
    }
}

// ---------------------------------------------------------------------------
// Kernel 3: loss = mean over 2B of [ log(denom + 1e-7) - pos / tau ]
// ---------------------------------------------------------------------------
__global__ void finalize_kernel(float* __restrict__ out) {
    __shared__ float sh[256];
    float s = 0.f;
    for (int i = threadIdx.x; i < N2; i += 256)
        s += logf(g_denom[i] + 1e-7f) - g_pos[i] * 2.0f;
    sh[threadIdx.x] = s;
    __syncthreads();
    for (int st = 128; st; st >>= 1) {
        if (threadIdx.x < st) sh[threadIdx.x] += sh[threadIdx.x + st];
        __syncthreads();
    }
    if (threadIdx.x == 0) out[0] = sh[0] / (float)N2;
}

// ---------------------------------------------------------------------------
extern "C" void kernel_launch(void* const* d_in, const int* in_sizes, int n_in,
                              void* d_out, int out_size) {
    const float* emb_i = (const float*)d_in[0];
    const float* emb_j = (const float*)d_in[1];
    const int*   traw  = (const int*)d_in[2];
    float* out = (float*)d_out;

    labels_kernel<<<1, 256>>>(traw);
    normalize_kernel<<<N2, 128>>>(emb_i, emb_j);
    simloss_kernel<<<N2 / TILE, 256>>>();
    finalize_kernel<<<1, 256>>>(out);
}

// round 4
// speedup vs baseline: 12.5715x; 12.5715x over previous
#include <cuda_runtime.h>
#include <cuda_bf16.h>
#include <stdint.h>
#include <math.h>

#define BSZ   4096
#define DDIM  512
#define N2    8192
#define MTILE 128
#define KC    64
#define NCH   256            // 32 j-tiles * 8 k-chunks

// smem layout
#define OFF_A    0           // 8 chunks x 16KB = 131072
#define OFF_B    131072      // 4 ring bufs x 16KB = 65536
#define OFF_LJ   196608      // 4096 ints = 16384
#define SMEM_TOTAL 212992

// ---------------- device scratch ----------------
__device__ __align__(256) __nv_bfloat16 g_repsb[(size_t)N2 * DDIM]; // 8 MB
__device__ int   g_labels[N2];
__device__ float g_pos[N2];
__device__ float g_denomp[8][N2];   // [jh*4 + wx][row]

// ---------------- helpers ----------------
__device__ __forceinline__ uint32_t smem_u32(const void* p) {
    return (uint32_t)__cvta_generic_to_shared(p);
}
__device__ __forceinline__ void cp16(uint32_t s, const void* g) {
    asm volatile("cp.async.cg.shared.global [%0], [%1], 16;"
                 :: "r"(s), "l"(__cvta_generic_to_global(g)) : "memory");
}
#define CP_COMMIT() asm volatile("cp.async.commit_group;" ::: "memory")
#define CP_WAIT(n)  asm volatile("cp.async.wait_group %0;" :: "n"(n) : "memory")

__device__ __forceinline__ uint32_t swz(uint32_t o) { return o ^ ((o >> 3) & 0x70); }

__device__ __forceinline__ void ldsm4(uint32_t* r, uint32_t addr) {
    asm volatile("ldmatrix.sync.aligned.m8n8.x4.shared.b16 {%0,%1,%2,%3}, [%4];"
                 : "=r"(r[0]), "=r"(r[1]), "=r"(r[2]), "=r"(r[3]) : "r"(addr));
}
__device__ __forceinline__ void mma16816(float* c, const uint32_t* a, const uint32_t* b) {
    asm volatile("mma.sync.aligned.m16n8k16.row.col.f32.bf16.bf16.f32 "
                 "{%0,%1,%2,%3}, {%4,%5,%6,%7}, {%8,%9}, {%0,%1,%2,%3};"
                 : "+f"(c[0]), "+f"(c[1]), "+f"(c[2]), "+f"(c[3])
                 : "r"(a[0]), "r"(a[1]), "r"(a[2]), "r"(a[3]), "r"(b[0]), "r"(b[1]));
}
__device__ __forceinline__ float ex2(float x) {
    float r; asm("ex2.approx.ftz.f32 %0, %1;" : "=f"(r) : "f"(x)); return r;
}

// ---------------------------------------------------------------------------
// Kernel 0: labels (robust to int32/int64 target buffer)
// ---------------------------------------------------------------------------
__global__ void labels_kernel(const int* __restrict__ traw) {
    __shared__ int odd_nonzero;
    if (threadIdx.x == 0) odd_nonzero = 0;
    __syncthreads();
    int local = 0;
    for (int i = threadIdx.x; i < BSZ / 2; i += 256)
        if (traw[2 * i + 1] != 0) local = 1;
    if (local) atomicOr(&odd_nonzero, 1);
    __syncthreads();
    const bool is64 = (odd_nonzero == 0);
    for (int i = threadIdx.x; i < BSZ; i += 256) {
        int v = is64 ? traw[2 * i] : traw[i];
        g_labels[i] = v;
        g_labels[i + BSZ] = v;
    }
}

// ---------------------------------------------------------------------------
// Kernel 1: per-pair normalize -> bf16 reps; fp32 positives
// ---------------------------------------------------------------------------
__global__ void normpos_kernel(const float* __restrict__ ei,
                               const float* __restrict__ ej) {
    int i = blockIdx.x;      // 0..4095
    int t = threadIdx.x;     // 128 threads
    float4 vi = reinterpret_cast<const float4*>(ei + (size_t)i * DDIM)[t];
    float4 vj = reinterpret_cast<const float4*>(ej + (size_t)i * DDIM)[t];
    float si = vi.x*vi.x + vi.y*vi.y + vi.z*vi.z + vi.w*vi.w;
    float sj = vj.x*vj.x + vj.y*vj.y + vj.z*vj.z + vj.w*vj.w;
    float dp = vi.x*vj.x + vi.y*vj.y + vi.z*vj.z + vi.w*vj.w;
#pragma unroll
    for (int o = 16; o; o >>= 1) {
        si += __shfl_xor_sync(0xffffffffu, si, o);
        sj += __shfl_xor_sync(0xffffffffu, sj, o);
        dp += __shfl_xor_sync(0xffffffffu, dp, o);
    }
    __shared__ float sm[3][4];
    int w = t >> 5;
    if ((t & 31) == 0) { sm[0][w] = si; sm[1][w] = sj; sm[2][w] = dp; }
    __syncthreads();
    si = sm[0][0] + sm[0][1] + sm[0][2] + sm[0][3];
    sj = sm[1][0] + sm[1][1] + sm[1][2] + sm[1][3];
    dp = sm[2][0] + sm[2][1] + sm[2][2] + sm[2][3];
    float ri = 1.0f / fmaxf(sqrtf(si), 1e-12f);
    float rj = 1.0f / fmaxf(sqrtf(sj), 1e-12f);

    __nv_bfloat162* oi = reinterpret_cast<__nv_bfloat162*>(g_repsb + (size_t)i * DDIM);
    __nv_bfloat162* oj = reinterpret_cast<__nv_bfloat162*>(g_repsb + (size_t)(i + BSZ) * DDIM);
    __nv_bfloat162 h;
    h.x = __float2bfloat16(vi.x * ri); h.y = __float2bfloat16(vi.y * ri); oi[2*t]   = h;
    h.x = __float2bfloat16(vi.z * ri); h.y = __float2bfloat16(vi.w * ri); oi[2*t+1] = h;
    h.x = __float2bfloat16(vj.x * rj); h.y = __float2bfloat16(vj.y * rj); oj[2*t]   = h;
    h.x = __float2bfloat16(vj.z * rj); h.y = __float2bfloat16(vj.w * rj); oj[2*t+1] = h;
    if (t == 0) {
        float pos = dp * ri * rj;
        g_pos[i] = pos;
        g_pos[i + BSZ] = pos;
    }
}

// ---------------------------------------------------------------------------
// Kernel 2: fused mma.sync bf16 sim-GEMM + mask + exp + row-sum
// grid = 128: (i-tile 0..63) x (j-half 0..1). 256 threads = 8 warps.
// warp (wy,wx): rows [wy*64, +64), cols [wx*32, +32) of the 128x128 tile.
// ---------------------------------------------------------------------------
__global__ void __launch_bounds__(256, 1) simloss_kernel() {
    extern __shared__ __align__(1024) char smem[];
    const uint32_t sb = smem_u32(smem);
    const int tid  = threadIdx.x;
    const int wid  = tid >> 5;
    const int lane = tid & 31;
    const int wx = wid & 3, wy = wid >> 2;
    const int iBase  = (blockIdx.x >> 1) * MTILE;
    const int jh     = blockIdx.x & 1;
    const int jStart = jh * 4096;

    int* ljS = reinterpret_cast<int*>(smem + OFF_LJ);

    // ---- prologue: full A (8 chunks) + B chunk 0 -> group0; B chunk1 -> group1
#pragma unroll
    for (int x = 0; x < 32; ++x) {
        int u = tid + x * 256;                  // 16B units of A (8192 total)
        int ch = u >> 10, v = u & 1023;
        int rowb = v >> 3, c16 = v & 7;
        uint32_t so = sb + OFF_A + ch * 16384 + swz(rowb * 128 + c16 * 16);
        cp16(so, g_repsb + (size_t)(iBase + rowb) * DDIM + ch * KC + c16 * 8);
    }
    {
        const __nv_bfloat16* gb = g_repsb + (size_t)jStart * DDIM;     // chunk 0
#pragma unroll
        for (int x = 0; x < 4; ++x) {
            int u = tid + x * 256;
            int rowb = u >> 3, c16 = u & 7;
            cp16(sb + OFF_B + swz(rowb * 128 + c16 * 16),
                 gb + (size_t)rowb * DDIM + c16 * 8);
        }
    }
    CP_COMMIT();
    {
        const __nv_bfloat16* gb = g_repsb + (size_t)jStart * DDIM + KC;  // chunk 1 (jt0,kc1)
#pragma unroll
        for (int x = 0; x < 4; ++x) {
            int u = tid + x * 256;
            int rowb = u >> 3, c16 = u & 7;
            cp16(sb + OFF_B + 16384 + swz(rowb * 128 + c16 * 16),
                 gb + (size_t)rowb * DDIM + c16 * 8);
        }
    }
    CP_COMMIT();

    // labels for this j-half
    for (int i = tid; i < 4096; i += 256) ljS[i] = g_labels[jStart + i];

    // per-lane fragment address pieces (byte offsets inside a 16KB chunk)
    const int arow = lane & 15;
    const int acolb = (lane >> 4) * 16;
    const int brow = (lane & 7) + ((lane >> 4) & 1) * 8;
    const int bcolb = ((lane >> 3) & 1) * 16;
    uint32_t aOff[4], bOff[2];
#pragma unroll
    for (int mf = 0; mf < 4; ++mf)
        aOff[mf] = (wy * 64 + mf * 16 + arow) * 128 + acolb;
#pragma unroll
    for (int nf2 = 0; nf2 < 2; ++nf2)
        bOff[nf2] = (wx * 32 + nf2 * 16 + brow) * 128 + bcolb;

    // row identity (constant across j)
    const int q = lane >> 2;
    int li0[4], li1[4];
#pragma unroll
    for (int mf = 0; mf < 4; ++mf) {
        li0[mf] = g_labels[iBase + wy * 64 + mf * 16 + q];
        li1[mf] = g_labels[iBase + wy * 64 + mf * 16 + q + 8];
    }

    float acc[4][4][4];
    float rs[4][2] = {};

    for (int c = 0; c < NCH; ++c) {
        const int ch = c & 7, jt = c >> 3, buf = c & 3;

        if (c + 2 < NCH) {         // depth-2 prefetch into ring-4
            const int nc = c + 2;
            const int njt = nc >> 3, nkc = nc & 7;
            const __nv_bfloat16* gb =
                g_repsb + (size_t)(jStart + njt * 128) * DDIM + nkc * KC;
            uint32_t sB = sb + OFF_B + (nc & 3) * 16384;
#pragma unroll
            for (int x = 0; x < 4; ++x) {
                int u = tid + x * 256;
                int rowb = u >> 3, c16 = u & 7;
                cp16(sB + swz(rowb * 128 + c16 * 16), gb + (size_t)rowb * DDIM + c16 * 8);
            }
            CP_COMMIT();
            CP_WAIT(2);
        } else if (c + 1 < NCH) {
            CP_WAIT(1);
        } else {
            CP_WAIT(0);
        }
        __syncthreads();

        if (ch == 0) {
#pragma unroll
            for (int mf = 0; mf < 4; ++mf)
#pragma unroll
                for (int nf = 0; nf < 4; ++nf)
#pragma unroll
                    for (int e = 0; e < 4; ++e) acc[mf][nf][e] = 0.0f;
        }

        const uint32_t sA = sb + OFF_A + ch * 16384;
        const uint32_t sB = sb + OFF_B + buf * 16384;
#pragma unroll
        for (int ks = 0; ks < 4; ++ks) {
            uint32_t a[4][4], b[2][4];
#pragma unroll
            for (int mf = 0; mf < 4; ++mf) ldsm4(a[mf], sA + swz(aOff[mf] + ks * 32));
#pragma unroll
            for (int nf2 = 0; nf2 < 2; ++nf2) ldsm4(b[nf2], sB + swz(bOff[nf2] + ks * 32));
#pragma unroll
            for (int mf = 0; mf < 4; ++mf)
#pragma unroll
                for (int nf = 0; nf < 4; ++nf)
                    mma16816(acc[mf][nf], a[mf], &b[nf >> 1][(nf & 1) * 2]);
        }

        if (ch == 7) {   // epilogue for tile jt
#pragma unroll
            for (int mf = 0; mf < 4; ++mf) {
                const int gi0 = iBase + wy * 64 + mf * 16 + q;
                const int gi1 = gi0 + 8;
                const int l0 = li0[mf], l1 = li1[mf];
                float s0 = 0.f, s1 = 0.f;
#pragma unroll
                for (int nf = 0; nf < 4; ++nf) {
                    const int cb = jt * 128 + wx * 32 + nf * 8 + (lane & 3) * 2;
                    const int lj0 = ljS[cb], lj1 = ljS[cb + 1];
                    const int gj0 = jStart + cb, gj1 = gj0 + 1;
                    const float* cc = acc[mf][nf];
                    {
                        int d = gi0 - gj0;
                        bool ex = (d == 0) || ((l0 == lj0) && (d != BSZ) && (d != -BSZ));
                        if (!ex) s0 += ex2(cc[0] * 2.885390081777927f);
                    }
                    {
                        int d = gi0 - gj1;
                        bool ex = (d == 0) || ((l0 == lj1) && (d != BSZ) && (d != -BSZ));
                        if (!ex) s0 += ex2(cc[1] * 2.885390081777927f);
                    }
                    {
                        int d = gi1 - gj0;
                        bool ex = (d == 0) || ((l1 == lj0) && (d != BSZ) && (d != -BSZ));
                        if (!ex) s1 += ex2(cc[2] * 2.885390081777927f);
                    }
                    {
                        int d = gi1 - gj1;
                        bool ex = (d == 0) || ((l1 == lj1) && (d != BSZ) && (d != -BSZ));
                        if (!ex) s1 += ex2(cc[3] * 2.885390081777927f);
                    }
                }
                rs[mf][0] += s0;
                rs[mf][1] += s1;
            }
        }
        __syncthreads();   // WAR fence: ring buf reused 4 iterations later
    }

    // reduce row sums across the 4 lanes of each quad-column group
#pragma unroll
    for (int mf = 0; mf < 4; ++mf) {
        float r0 = rs[mf][0], r1 = rs[mf][1];
        r0 += __shfl_xor_sync(0xffffffffu, r0, 1);
        r0 += __shfl_xor_sync(0xffffffffu, r0, 2);
        r1 += __shfl_xor_sync(0xffffffffu, r1, 1);
        r1 += __shfl_xor_sync(0xffffffffu, r1, 2);
        if ((lane & 3) == 0) {
            int row = iBase + wy * 64 + mf * 16 + q;
            g_denomp[jh * 4 + wx][row] = r0;
            g_denomp[jh * 4 + wx][row + 8] = r1;
        }
    }
}

// ---------------------------------------------------------------------------
// Kernel 3: loss = mean over 2B of [ log(denom + 1e-7) - 2*pos ]
// ---------------------------------------------------------------------------
__global__ void finalize_kernel(float* __restrict__ out) {
    __shared__ float sh[256];
    float s = 0.0f;
    for (int i = threadIdx.x; i < N2; i += 256) {
        float den = 0.f;
#pragma unroll
        for (int p = 0; p < 8; ++p) den += g_denomp[p][i];
        s += logf(den + 1e-7f) - 2.0f * g_pos[i];
    }
    sh[threadIdx.x] = s;
    __syncthreads();
    for (int st = 128; st; st >>= 1) {
        if (threadIdx.x < st) sh[threadIdx.x] += sh[threadIdx.x + st];
        __syncthreads();
    }
    if (threadIdx.x == 0) out[0] = sh[0] / (float)N2;
}

// ---------------------------------------------------------------------------
extern "C" void kernel_launch(void* const* d_in, const int* in_sizes, int n_in,
                              void* d_out, int out_size) {
    const float* emb_i = (const float*)d_in[0];
    const float* emb_j = (const float*)d_in[1];
    const int*   traw  = (const int*)d_in[2];
    float* out = (float*)d_out;

    cudaFuncSetAttribute(simloss_kernel,
                         cudaFuncAttributeMaxDynamicSharedMemorySize, SMEM_TOTAL);

    labels_kernel<<<1, 256>>>(traw);
    normpos_kernel<<<BSZ, 128>>>(emb_i, emb_j);
    simloss_kernel<<<128, 256, SMEM_TOTAL>>>();
    finalize_kernel<<<1, 256>>>(out);
}

// round 7
// speedup vs baseline: 21.5519x; 1.7143x over previous
#include <cuda_runtime.h>
#include <cuda_fp16.h>
#include <stdint.h>
#include <math.h>

#define BSZ   4096
#define DDIM  512
#define N2    8192
#define MTILE 128
#define KC    64
#define NPAIR 128            // 128 pair-iterations (2 chunks each)

// smem layout (bytes)
#define OFF_A    0           // 8 chunks x 16KB = 131072
#define OFF_B    131072      // 3 pairs x 32KB  = 98304  (ring of 6 chunks)
#define OFF_LJ   229376      // 128 ints = 512
#define SMEM_TOTAL 230400    // <= 232448 dynamic limit

#define NSCALE 1.698644f     // sqrt(2/ln2): folds exp(2s)=2^(c*s) scale into reps

// ---------------- device scratch ----------------
__device__ __align__(256) __half g_repsh[(size_t)N2 * DDIM];  // 8 MB
__device__ int   g_labels[N2];
__device__ float g_pos[N2];
__device__ float g_denomp[8][N2];   // [jh*4 + wx][row]
__device__ int   g_arrive;          // zero-init, reset by last CTA

// ---------------- helpers ----------------
__device__ __forceinline__ uint32_t smem_u32(const void* p) {
    return (uint32_t)__cvta_generic_to_shared(p);
}
__device__ __forceinline__ void cp16(uint32_t s, const void* g) {
    asm volatile("cp.async.cg.shared.global [%0], [%1], 16;"
                 :: "r"(s), "l"(__cvta_generic_to_global(g)) : "memory");
}
#define CP_COMMIT() asm volatile("cp.async.commit_group;" ::: "memory")
#define CP_WAIT(n)  asm volatile("cp.async.wait_group %0;" :: "n"(n) : "memory")

__device__ __forceinline__ uint32_t swz(uint32_t o) { return o ^ ((o >> 3) & 0x70); }

__device__ __forceinline__ void ldsm4(uint32_t* r, uint32_t addr) {
    asm volatile("ldmatrix.sync.aligned.m8n8.x4.shared.b16 {%0,%1,%2,%3}, [%4];"
                 : "=r"(r[0]), "=r"(r[1]), "=r"(r[2]), "=r"(r[3]) : "r"(addr));
}
// f16 x f16 -> f16 accumulate (acc packed half2 x2)
__device__ __forceinline__ void mma16816h(uint32_t* c, const uint32_t* a, const uint32_t* b) {
    asm volatile("mma.sync.aligned.m16n8k16.row.col.f16.f16.f16.f16 "
                 "{%0,%1}, {%2,%3,%4,%5}, {%6,%7}, {%0,%1};"
                 : "+r"(c[0]), "+r"(c[1])
                 : "r"(a[0]), "r"(a[1]), "r"(a[2]), "r"(a[3]), "r"(b[0]), "r"(b[1]));
}
__device__ __forceinline__ float ex2(float x) {
    float r; asm("ex2.approx.ftz.f32 %0, %1;" : "=f"(r) : "f"(x)); return r;
}
__device__ __forceinline__ float lg2(float x) {
    float r; asm("lg2.approx.f32 %0, %1;" : "=f"(r) : "f"(x)); return r;
}

// ---------------------------------------------------------------------------
// Kernel 0: labels (robust to int32/int64 target buffer)
// ---------------------------------------------------------------------------
__global__ void labels_kernel(const int* __restrict__ traw) {
    __shared__ int odd_nonzero;
    if (threadIdx.x == 0) odd_nonzero = 0;
    __syncthreads();
    int local = 0;
    for (int i = threadIdx.x; i < BSZ / 2; i += 256)
        if (traw[2 * i + 1] != 0) local = 1;
    if (local) atomicOr(&odd_nonzero, 1);
    __syncthreads();
    const bool is64 = (odd_nonzero == 0);
    for (int i = threadIdx.x; i < BSZ; i += 256) {
        int v = is64 ? traw[2 * i] : traw[i];
        g_labels[i] = v;
        g_labels[i + BSZ] = v;
    }
}

// ---------------------------------------------------------------------------
// Kernel 1: per-pair normalize -> f16 reps scaled by NSCALE; fp32 positives
// ---------------------------------------------------------------------------
__global__ void normpos_kernel(const float* __restrict__ ei,
                               const float* __restrict__ ej) {
    int i = blockIdx.x;      // 0..4095
    int t = threadIdx.x;     // 128 threads
    float4 vi = reinterpret_cast<const float4*>(ei + (size_t)i * DDIM)[t];
    float4 vj = reinterpret_cast<const float4*>(ej + (size_t)i * DDIM)[t];
    float si = vi.x*vi.x + vi.y*vi.y + vi.z*vi.z + vi.w*vi.w;
    float sj = vj.x*vj.x + vj.y*vj.y + vj.z*vj.z + vj.w*vj.w;
    float dp = vi.x*vj.x + vi.y*vj.y + vi.z*vj.z + vi.w*vj.w;
#pragma unroll
    for (int o = 16; o; o >>= 1) {
        si += __shfl_xor_sync(0xffffffffu, si, o);
        sj += __shfl_xor_sync(0xffffffffu, sj, o);
        dp += __shfl_xor_sync(0xffffffffu, dp, o);
    }
    __shared__ float sm[3][4];
    int w = t >> 5;
    if ((t & 31) == 0) { sm[0][w] = si; sm[1][w] = sj; sm[2][w] = dp; }
    __syncthreads();
    si = sm[0][0] + sm[0][1] + sm[0][2] + sm[0][3];
    sj = sm[1][0] + sm[1][1] + sm[1][2] + sm[1][3];
    dp = sm[2][0] + sm[2][1] + sm[2][2] + sm[2][3];
    float ri = NSCALE / fmaxf(sqrtf(si), 1e-12f);
    float rj = NSCALE / fmaxf(sqrtf(sj), 1e-12f);

    __half2* oi = reinterpret_cast<__half2*>(g_repsh + (size_t)i * DDIM);
    __half2* oj = reinterpret_cast<__half2*>(g_repsh + (size_t)(i + BSZ) * DDIM);
    oi[2*t]   = __floats2half2_rn(vi.x * ri, vi.y * ri);
    oi[2*t+1] = __floats2half2_rn(vi.z * ri, vi.w * ri);
    oj[2*t]   = __floats2half2_rn(vj.x * rj, vj.y * rj);
    oj[2*t+1] = __floats2half2_rn(vj.z * rj, vj.w * rj);
    if (t == 0) {
        float pos = (dp / NSCALE / NSCALE) * (ri * rj);  // fp32 exact positive
        g_pos[i] = pos;
        g_pos[i + BSZ] = pos;
    }
}

// ---------------------------------------------------------------------------
// Kernel 2: fused mma.sync f16 sim-GEMM + mask + exp + row-sum + finalize.
// grid = 128: (i-tile 0..63) x (j-half 0..1). 512 threads = 16 warps.
// warp (wy,wx): rows [wy*32,+32), cols [wx*32,+32) of the 128x128 tile.
// ---------------------------------------------------------------------------
__global__ void __launch_bounds__(512, 1) simloss_kernel(float* __restrict__ out) {
    extern __shared__ __align__(1024) char smem[];
    const uint32_t sb = smem_u32(smem);
    const int tid  = threadIdx.x;
    const int wid  = tid >> 5;
    const int lane = tid & 31;
    const int wx = wid & 3, wy = wid >> 2;
    const int iBase  = (blockIdx.x >> 1) * MTILE;
    const int jh     = blockIdx.x & 1;
    const int jStart = jh * 4096;

    int* ljS = reinterpret_cast<int*>(smem + OFF_LJ);

    // special (positive-pair) j-tile index within this half, or -1
    const int posCol = (iBase < BSZ) ? iBase + BSZ : iBase - BSZ;
    const int sjt = (posCol >= jStart && posCol < jStart + 4096)
                        ? ((posCol - jStart) >> 7) : -1;
    const int pdelta = (iBase < BSZ) ? BSZ : -BSZ;

    // ---- prologue: G0 = A(all 8 chunks) + B pair0 (chunks 0,1); G1 = pair1 ----
#pragma unroll
    for (int x = 0; x < 16; ++x) {
        int u = tid + x * 512;                  // 16B units of A (8192 total)
        int ch = u >> 10, v = u & 1023;
        int rowb = v >> 3, c16 = v & 7;
        cp16(sb + OFF_A + ch * 16384 + swz(rowb * 128 + c16 * 16),
             g_repsh + (size_t)(iBase + rowb) * DDIM + ch * KC + c16 * 8);
    }
#pragma unroll
    for (int x = 0; x < 4; ++x) {               // chunks 0,1 -> pair 0
        int u = tid + x * 512;
        int k = u >> 10, v = u & 1023;
        int rowb = v >> 3, c16 = v & 7;
        cp16(sb + OFF_B + k * 16384 + swz(rowb * 128 + c16 * 16),
             g_repsh + (size_t)(jStart + (k >> 3) * 128 + rowb) * DDIM + (k & 7) * KC + c16 * 8);
    }
    CP_COMMIT();
#pragma unroll
    for (int x = 0; x < 4; ++x) {               // chunks 2,3 -> pair 1
        int u = tid + x * 512;
        int kk = u >> 10, v = u & 1023;
        int k = kk + 2;
        int rowb = v >> 3, c16 = v & 7;
        cp16(sb + OFF_B + 32768 + kk * 16384 + swz(rowb * 128 + c16 * 16),
             g_repsh + (size_t)(jStart + (k >> 3) * 128 + rowb) * DDIM + (k & 7) * KC + c16 * 8);
    }
    CP_COMMIT();

    // fragment address pieces
    const int arow  = lane & 15;
    const int acolb = (lane >> 4) * 16;
    const int brow  = (lane & 7) + ((lane >> 4) & 1) * 8;
    const int bcolb = ((lane >> 3) & 1) * 16;
    uint32_t aOff[2], bOff[2];
#pragma unroll
    for (int mf = 0; mf < 2; ++mf)
        aOff[mf] = (wy * 32 + mf * 16 + arow) * 128 + acolb;
#pragma unroll
    for (int nf2 = 0; nf2 < 2; ++nf2)
        bOff[nf2] = (wx * 32 + nf2 * 16 + brow) * 128 + bcolb;

    // row identity
    const int q = lane >> 2;
    const int t4 = lane & 3;
    int l0[2], l1[2];
#pragma unroll
    for (int mf = 0; mf < 2; ++mf) {
        l0[mf] = g_labels[iBase + wy * 32 + mf * 16 + q];
        l1[mf] = g_labels[iBase + wy * 32 + mf * 16 + q + 8];
    }

    uint32_t acc[2][4][2];     // f16x2 accumulators
    float rs[2][2] = {};       // row sums: [mf][rowhalf]
    int pbuf = 0;              // ring pair index (mod 3)

    for (int i = 0; i < NPAIR; ++i) {
        const int jt = i >> 2;
        const int ck0 = (2 * i) & 7;

        if (i < NPAIR - 1) CP_WAIT(1); else CP_WAIT(0);
        __syncthreads();

        if ((i & 3) == 0 && tid < 128)
            ljS[tid] = g_labels[jStart + jt * 128 + tid];

        // prefetch pair for iteration i+2 into ring slot (pbuf+2)%3
        if (i + 2 < NPAIR) {
            const int fp = (pbuf + 2 >= 3) ? pbuf - 1 : pbuf + 2;
            const int base_k = 2 * (i + 2);
#pragma unroll
            for (int x = 0; x < 4; ++x) {
                int u = tid + x * 512;
                int kk = u >> 10, v = u & 1023;
                int k = base_k + kk;
                int rowb = v >> 3, c16 = v & 7;
                cp16(sb + OFF_B + fp * 32768 + kk * 16384 + swz(rowb * 128 + c16 * 16),
                     g_repsh + (size_t)(jStart + (k >> 3) * 128 + rowb) * DDIM +
                         (k & 7) * KC + c16 * 8);
            }
            CP_COMMIT();
        }

        if ((i & 3) == 0) {
#pragma unroll
            for (int mf = 0; mf < 2; ++mf)
#pragma unroll
                for (int nf = 0; nf < 4; ++nf)
                    acc[mf][nf][0] = acc[mf][nf][1] = 0u;
        }

        // ---- compute two K chunks ----
#pragma unroll
        for (int cc = 0; cc < 2; ++cc) {
            const uint32_t sA = sb + OFF_A + (ck0 + cc) * 16384;
            const uint32_t sB = sb + OFF_B + pbuf * 32768 + cc * 16384;
#pragma unroll
            for (int ks = 0; ks < 4; ++ks) {
                uint32_t a[2][4], b[2][4];
#pragma unroll
                for (int mf = 0; mf < 2; ++mf) ldsm4(a[mf], sA + swz(aOff[mf] + ks * 32));
#pragma unroll
                for (int nf2 = 0; nf2 < 2; ++nf2) ldsm4(b[nf2], sB + swz(bOff[nf2] + ks * 32));
#pragma unroll
                for (int mf = 0; mf < 2; ++mf)
#pragma unroll
                    for (int nf = 0; nf < 4; ++nf)
                        mma16816h(acc[mf][nf], a[mf], &b[nf >> 1][(nf & 1) * 2]);
            }
        }

        // ---- epilogue at tile end ----
        if ((i & 3) == 3) {
            const bool special = (jt == sjt);
            const int colBase = jStart + jt * 128;
#pragma unroll
            for (int mf = 0; mf < 2; ++mf) {
                const int gi0 = iBase + wy * 32 + mf * 16 + q;
                const int la = l0[mf], lb = l1[mf];
                float s0 = 0.f, s1 = 0.f;
                if (!special) {
#pragma unroll
                    for (int nf = 0; nf < 4; ++nf) {
                        const int c0 = wx * 32 + nf * 8 + t4 * 2;
                        const int lj0 = ljS[c0], lj1 = ljS[c0 + 1];
                        float2 v0 = __half22float2(*(__half2*)&acc[mf][nf][0]);
                        float2 v1 = __half22float2(*(__half2*)&acc[mf][nf][1]);
                        float e00 = ex2(v0.x), e01 = ex2(v0.y);
                        float e10 = ex2(v1.x), e11 = ex2(v1.y);
                        if (la != lj0) s0 += e00;
                        if (la != lj1) s0 += e01;
                        if (lb != lj0) s1 += e10;
                        if (lb != lj1) s1 += e11;
                    }
                } else {
                    const int pc0 = gi0 + pdelta, pc1 = gi0 + 8 + pdelta;
#pragma unroll
                    for (int nf = 0; nf < 4; ++nf) {
                        const int c0 = wx * 32 + nf * 8 + t4 * 2;
                        const int lj0 = ljS[c0], lj1 = ljS[c0 + 1];
                        const int gj0 = colBase + c0, gj1 = gj0 + 1;
                        float2 v0 = __half22float2(*(__half2*)&acc[mf][nf][0]);
                        float2 v1 = __half22float2(*(__half2*)&acc[mf][nf][1]);
                        float e00 = ex2(v0.x), e01 = ex2(v0.y);
                        float e10 = ex2(v1.x), e11 = ex2(v1.y);
                        if (la != lj0 || gj0 == pc0) {} else e00 = 0.f;
                        if (la != lj1 || gj1 == pc0) {} else e01 = 0.f;
                        if (lb != lj0 || gj0 == pc1) {} else e10 = 0.f;
                        if (lb != lj1 || gj1 == pc1) {} else e11 = 0.f;
                        s0 += e00 + e01;
                        s1 += e10 + e11;
                    }
                }
                rs[mf][0] += s0;
                rs[mf][1] += s1;
            }
        }
        pbuf = (pbuf == 2) ? 0 : pbuf + 1;
    }

    // reduce row sums across the 4 lanes of each quad-column group
#pragma unroll
    for (int mf = 0; mf < 2; ++mf) {
        float r0 = rs[mf][0], r1 = rs[mf][1];
        r0 += __shfl_xor_sync(0xffffffffu, r0, 1);
        r0 += __shfl_xor_sync(0xffffffffu, r0, 2);
        r1 += __shfl_xor_sync(0xffffffffu, r1, 1);
        r1 += __shfl_xor_sync(0xffffffffu, r1, 2);
        if (t4 == 0) {
            int row = iBase + wy * 32 + mf * 16 + q;
            g_denomp[jh * 4 + wx][row] = r0;
            g_denomp[jh * 4 + wx][row + 8] = r1;
        }
    }

    // ---- last CTA computes the final loss ----
    __threadfence();
    __shared__ int amLast;
    if (tid == 0) amLast = (atomicAdd(&g_arrive, 1) == gridDim.x - 1);
    __syncthreads();
    if (amLast) {
        __threadfence();
        float s = 0.0f;
        for (int i = tid; i < N2; i += 512) {
            float den = 0.f;
#pragma unroll
            for (int p = 0; p < 8; ++p) den += g_denomp[p][i];
            s += lg2(den + 1e-7f) * 0.6931471805599453f - 2.0f * g_pos[i];
        }
        float* red = reinterpret_cast<float*>(smem + OFF_B);
        red[tid] = s;
        __syncthreads();
        for (int st = 256; st; st >>= 1) {
            if (tid < st) red[tid] += red[tid + st];
            __syncthreads();
        }
        if (tid == 0) {
            out[0] = red[0] / (float)N2;
            g_arrive = 0;
        }
    }
}

// ---------------------------------------------------------------------------
extern "C" void kernel_launch(void* const* d_in, const int* in_sizes, int n_in,
                              void* d_out, int out_size) {
    const float* emb_i = (const float*)d_in[0];
    const float* emb_j = (const float*)d_in[1];
    const int*   traw  = (const int*)d_in[2];
    float* out = (float*)d_out;

    cudaFuncSetAttribute(simloss_kernel,
                         cudaFuncAttributeMaxDynamicSharedMemorySize, SMEM_TOTAL);

    labels_kernel<<<1, 256>>>(traw);
    normpos_kernel<<<BSZ, 128>>>(emb_i, emb_j);
    simloss_kernel<<<128, 512, SMEM_TOTAL>>>(out);
}

// round 8
// speedup vs baseline: 23.0310x; 1.0686x over previous
#include <cuda_runtime.h>
#include <cuda_fp16.h>
#include <stdint.h>
#include <math.h>

#define BSZ   4096
#define DDIM  512
#define N2    8192
#define MTILE 128
#define KC    64
#define NIT   128            // 16 j-tiles (256 cols) * 8 k-chunks

// smem layout (bytes)
#define OFF_A    0           // 8 chunks x 16KB = 131072
#define OFF_B    131072      // 3 slots x 32KB (256 rows x 64K) = 98304
#define OFF_LJ   229376      // 256 ints = 1024
#define SMEM_TOTAL 230400

#define NSCALE 1.698644f     // sqrt(2/ln2): folds exp(2s)=2^(c*s) scale into reps

// ---------------- device scratch ----------------
__device__ __align__(256) __half g_repsh[(size_t)N2 * DDIM];  // 8 MB
__device__ int   g_labels[N2];
__device__ float g_pos[N2];
__device__ float g_denomp[8][N2];   // [jh*4 + wx][row]
__device__ int   g_arrive;          // zero-init, reset by last CTA

// ---------------- helpers ----------------
__device__ __forceinline__ uint32_t smem_u32(const void* p) {
    return (uint32_t)__cvta_generic_to_shared(p);
}
__device__ __forceinline__ void cp16(uint32_t s, const void* g) {
    asm volatile("cp.async.cg.shared.global [%0], [%1], 16;"
                 :: "r"(s), "l"(__cvta_generic_to_global(g)) : "memory");
}
#define CP_COMMIT() asm volatile("cp.async.commit_group;" ::: "memory")
#define CP_WAIT(n)  asm volatile("cp.async.wait_group %0;" :: "n"(n) : "memory")

__device__ __forceinline__ uint32_t swz(uint32_t o) { return o ^ ((o >> 3) & 0x70); }

__device__ __forceinline__ void ldsm4(uint32_t* r, uint32_t addr) {
    asm volatile("ldmatrix.sync.aligned.m8n8.x4.shared.b16 {%0,%1,%2,%3}, [%4];"
                 : "=r"(r[0]), "=r"(r[1]), "=r"(r[2]), "=r"(r[3]) : "r"(addr));
}
__device__ __forceinline__ void mma16816h(uint32_t* c, const uint32_t* a, const uint32_t* b) {
    asm volatile("mma.sync.aligned.m16n8k16.row.col.f16.f16.f16.f16 "
                 "{%0,%1}, {%2,%3,%4,%5}, {%6,%7}, {%0,%1};"
                 : "+r"(c[0]), "+r"(c[1])
                 : "r"(a[0]), "r"(a[1]), "r"(a[2]), "r"(a[3]), "r"(b[0]), "r"(b[1]));
}
__device__ __forceinline__ float ex2(float x) {
    float r; asm("ex2.approx.ftz.f32 %0, %1;" : "=f"(r) : "f"(x)); return r;
}
__device__ __forceinline__ float lg2(float x) {
    float r; asm("lg2.approx.f32 %0, %1;" : "=f"(r) : "f"(x)); return r;
}

// ---------------------------------------------------------------------------
// Kernel 1: per-pair normalize -> f16 reps scaled by NSCALE; fp32 positives.
// Block 0 additionally decodes labels (robust to int32/int64 target buffer).
// ---------------------------------------------------------------------------
__global__ void normpos_kernel(const float* __restrict__ ei,
                               const float* __restrict__ ej,
                               const int* __restrict__ traw) {
    int i = blockIdx.x;      // 0..4095
    int t = threadIdx.x;     // 128 threads
    float4 vi = reinterpret_cast<const float4*>(ei + (size_t)i * DDIM)[t];
    float4 vj = reinterpret_cast<const float4*>(ej + (size_t)i * DDIM)[t];
    float si = vi.x*vi.x + vi.y*vi.y + vi.z*vi.z + vi.w*vi.w;
    float sj = vj.x*vj.x + vj.y*vj.y + vj.z*vj.z + vj.w*vj.w;
    float dp = vi.x*vj.x + vi.y*vj.y + vi.z*vj.z + vi.w*vj.w;
#pragma unroll
    for (int o = 16; o; o >>= 1) {
        si += __shfl_xor_sync(0xffffffffu, si, o);
        sj += __shfl_xor_sync(0xffffffffu, sj, o);
        dp += __shfl_xor_sync(0xffffffffu, dp, o);
    }
    __shared__ float sm[3][4];
    int w = t >> 5;
    if ((t & 31) == 0) { sm[0][w] = si; sm[1][w] = sj; sm[2][w] = dp; }
    __syncthreads();
    si = sm[0][0] + sm[0][1] + sm[0][2] + sm[0][3];
    sj = sm[1][0] + sm[1][1] + sm[1][2] + sm[1][3];
    dp = sm[2][0] + sm[2][1] + sm[2][2] + sm[2][3];
    float ri = NSCALE / fmaxf(sqrtf(si), 1e-12f);
    float rj = NSCALE / fmaxf(sqrtf(sj), 1e-12f);

    __half2* oi = reinterpret_cast<__half2*>(g_repsh + (size_t)i * DDIM);
    __half2* oj = reinterpret_cast<__half2*>(g_repsh + (size_t)(i + BSZ) * DDIM);
    oi[2*t]   = __floats2half2_rn(vi.x * ri, vi.y * ri);
    oi[2*t+1] = __floats2half2_rn(vi.z * ri, vi.w * ri);
    oj[2*t]   = __floats2half2_rn(vj.x * rj, vj.y * rj);
    oj[2*t+1] = __floats2half2_rn(vj.z * rj, vj.w * rj);
    if (t == 0) {
        float pos = (dp / NSCALE / NSCALE) * (ri * rj);  // fp32 exact positive
        g_pos[i] = pos;
        g_pos[i + BSZ] = pos;
    }

    // ---- block 0: decode labels (int32 vs int64 detection) ----
    if (i == 0) {
        __shared__ int odd_nonzero;
        if (t == 0) odd_nonzero = 0;
        __syncthreads();
        int local = 0;
        for (int k = t; k < BSZ / 2; k += 128)
            if (traw[2 * k + 1] != 0) local = 1;
        if (local) atomicOr(&odd_nonzero, 1);
        __syncthreads();
        const bool is64 = (odd_nonzero == 0);
        for (int k = t; k < BSZ; k += 128) {
            int v = is64 ? traw[2 * k] : traw[k];
            g_labels[k] = v;
            g_labels[k + BSZ] = v;
        }
    }
}

// ---------------------------------------------------------------------------
// Kernel 2: fused mma.sync f16 sim-GEMM + mask + exp + row-sum + finalize.
// grid = 128: (i-tile 0..63) x (j-half 0..1). 512 threads = 16 warps.
// CTA tile per j-step: 128 rows x 256 cols. warp (wy,wx): rows [wy*32,+32),
// cols [wx*64,+64). B chunks: 256 rows x 64 K (32KB), ring of 3, prefetch 2.
// ---------------------------------------------------------------------------
__global__ void __launch_bounds__(512, 1) simloss_kernel(float* __restrict__ out) {
    extern __shared__ __align__(1024) char smem[];
    const uint32_t sb = smem_u32(smem);
    const int tid  = threadIdx.x;
    const int wid  = tid >> 5;
    const int lane = tid & 31;
    const int wx = wid & 3, wy = wid >> 2;
    const int iBase  = (blockIdx.x >> 1) * MTILE;
    const int jh     = blockIdx.x & 1;
    const int jStart = jh * 4096;

    int* ljS = reinterpret_cast<int*>(smem + OFF_LJ);

    // positive-pair j-tile index within this half (256-col tiles), or -1
    const int posCol = (iBase < BSZ) ? iBase + BSZ : iBase - BSZ;
    const int sjt = (posCol >= jStart && posCol < jStart + 4096)
                        ? ((posCol - jStart) >> 8) : -1;
    const int pdelta = (iBase < BSZ) ? BSZ : -BSZ;

    // ---- prologue: G0 = A(all 8 chunks) + B chunk0; G1 = B chunk1 ----
#pragma unroll
    for (int x = 0; x < 16; ++x) {
        int u = tid + x * 512;                  // 16B units of A (8192 total)
        int ch = u >> 10, v = u & 1023;
        int rowb = v >> 3, c16 = v & 7;
        cp16(sb + OFF_A + ch * 16384 + swz(rowb * 128 + c16 * 16),
             g_repsh + (size_t)(iBase + rowb) * DDIM + ch * KC + c16 * 8);
    }
#pragma unroll
    for (int x = 0; x < 4; ++x) {               // B iter0: jt0, kc0
        int u = tid + x * 512;                  // 0..2047
        int rowb = u >> 3, c16 = u & 7;
        cp16(sb + OFF_B + swz(rowb * 128 + c16 * 16),
             g_repsh + (size_t)(jStart + rowb) * DDIM + c16 * 8);
    }
    CP_COMMIT();
#pragma unroll
    for (int x = 0; x < 4; ++x) {               // B iter1: jt0, kc1
        int u = tid + x * 512;
        int rowb = u >> 3, c16 = u & 7;
        cp16(sb + OFF_B + 32768 + swz(rowb * 128 + c16 * 16),
             g_repsh + (size_t)(jStart + rowb) * DDIM + KC + c16 * 8);
    }
    CP_COMMIT();

    // fragment address pieces
    const int arow  = lane & 15;
    const int acolb = (lane >> 4) * 16;
    const int brow  = (lane & 7) + ((lane >> 4) & 1) * 8;
    const int bcolb = ((lane >> 3) & 1) * 16;
    uint32_t aOff[2], bOff[4];
#pragma unroll
    for (int mf = 0; mf < 2; ++mf)
        aOff[mf] = (wy * 32 + mf * 16 + arow) * 128 + acolb;
#pragma unroll
    for (int nf2 = 0; nf2 < 4; ++nf2)
        bOff[nf2] = (wx * 64 + nf2 * 16 + brow) * 128 + bcolb;

    // row identity
    const int q = lane >> 2;
    const int t4 = lane & 3;
    int l0[2], l1[2];
#pragma unroll
    for (int mf = 0; mf < 2; ++mf) {
        l0[mf] = g_labels[iBase + wy * 32 + mf * 16 + q];
        l1[mf] = g_labels[iBase + wy * 32 + mf * 16 + q + 8];
    }

    uint32_t acc[2][8][2];     // f16x2 accumulators: 32 regs
    float rs[2][2] = {};       // row sums: [mf][rowhalf]
    int buf = 0;               // ring slot (mod 3)

    for (int i = 0; i < NIT; ++i) {
        const int jt = i >> 3;
        const int ch = i & 7;

        if (i < NIT - 1) CP_WAIT(1); else CP_WAIT(0);
        __syncthreads();

        if (ch == 0 && tid < 256)
            ljS[tid] = g_labels[jStart + jt * 256 + tid];

        // prefetch chunk for iteration i+2 into ring slot (buf+2)%3
        if (i + 2 < NIT) {
            const int fb = (buf + 2 >= 3) ? buf - 1 : buf + 2;
            const int njt = (i + 2) >> 3, nch = (i + 2) & 7;
            const __half* gb =
                g_repsh + (size_t)(jStart + njt * 256) * DDIM + nch * KC;
            uint32_t sB = sb + OFF_B + fb * 32768;
#pragma unroll
            for (int x = 0; x < 4; ++x) {
                int u = tid + x * 512;
                int rowb = u >> 3, c16 = u & 7;
                cp16(sB + swz(rowb * 128 + c16 * 16), gb + (size_t)rowb * DDIM + c16 * 8);
            }
            CP_COMMIT();
        }

        if (ch == 0) {
#pragma unroll
            for (int mf = 0; mf < 2; ++mf)
#pragma unroll
                for (int nf = 0; nf < 8; ++nf)
                    acc[mf][nf][0] = acc[mf][nf][1] = 0u;
        }

        // ---- compute one 64-K chunk over 256 cols ----
        {
            const uint32_t sA = sb + OFF_A + ch * 16384;
            const uint32_t sB = sb + OFF_B + buf * 32768;
#pragma unroll
            for (int ks = 0; ks < 4; ++ks) {
                uint32_t a[2][4], b[4][4];
#pragma unroll
                for (int mf = 0; mf < 2; ++mf) ldsm4(a[mf], sA + swz(aOff[mf] + ks * 32));
#pragma unroll
                for (int nf2 = 0; nf2 < 4; ++nf2) ldsm4(b[nf2], sB + swz(bOff[nf2] + ks * 32));
#pragma unroll
                for (int mf = 0; mf < 2; ++mf)
#pragma unroll
                    for (int nf = 0; nf < 8; ++nf)
                        mma16816h(acc[mf][nf], a[mf], &b[nf >> 1][(nf & 1) * 2]);
            }
        }

        // ---- epilogue at tile end ----
        if (ch == 7) {
            const bool special = (jt == sjt);
            const int colBase = jStart + jt * 256;
#pragma unroll
            for (int mf = 0; mf < 2; ++mf) {
                const int gi0 = iBase + wy * 32 + mf * 16 + q;
                const int la = l0[mf], lb = l1[mf];
                float s0 = 0.f, s1 = 0.f;
                if (!special) {
#pragma unroll
                    for (int nf = 0; nf < 8; ++nf) {
                        const int c0 = wx * 64 + nf * 8 + t4 * 2;
                        const int lj0 = ljS[c0], lj1 = ljS[c0 + 1];
                        float2 v0 = __half22float2(*(__half2*)&acc[mf][nf][0]);
                        float2 v1 = __half22float2(*(__half2*)&acc[mf][nf][1]);
                        float e00 = ex2(v0.x), e01 = ex2(v0.y);
                        float e10 = ex2(v1.x), e11 = ex2(v1.y);
                        if (la != lj0) s0 += e00;
                        if (la != lj1) s0 += e01;
                        if (lb != lj0) s1 += e10;
                        if (lb != lj1) s1 += e11;
                    }
                } else {
                    const int pc0 = gi0 + pdelta, pc1 = gi0 + 8 + pdelta;
#pragma unroll
                    for (int nf = 0; nf < 8; ++nf) {
                        const int c0 = wx * 64 + nf * 8 + t4 * 2;
                        const int lj0 = ljS[c0], lj1 = ljS[c0 + 1];
                        const int gj0 = colBase + c0, gj1 = gj0 + 1;
                        float2 v0 = __half22float2(*(__half2*)&acc[mf][nf][0]);
                        float2 v1 = __half22float2(*(__half2*)&acc[mf][nf][1]);
                        float e00 = ex2(v0.x), e01 = ex2(v0.y);
                        float e10 = ex2(v1.x), e11 = ex2(v1.y);
                        if (la != lj0 || gj0 == pc0) {} else e00 = 0.f;
                        if (la != lj1 || gj1 == pc0) {} else e01 = 0.f;
                        if (lb != lj0 || gj0 == pc1) {} else e10 = 0.f;
                        if (lb != lj1 || gj1 == pc1) {} else e11 = 0.f;
                        s0 += e00 + e01;
                        s1 += e10 + e11;
                    }
                }
                rs[mf][0] += s0;
                rs[mf][1] += s1;
            }
        }
        buf = (buf == 2) ? 0 : buf + 1;
    }

    // reduce row sums across the 4 lanes of each quad-column group
#pragma unroll
    for (int mf = 0; mf < 2; ++mf) {
        float r0 = rs[mf][0], r1 = rs[mf][1];
        r0 += __shfl_xor_sync(0xffffffffu, r0, 1);
        r0 += __shfl_xor_sync(0xffffffffu, r0, 2);
        r1 += __shfl_xor_sync(0xffffffffu, r1, 1);
        r1 += __shfl_xor_sync(0xffffffffu, r1, 2);
        if (t4 == 0) {
            int row = iBase + wy * 32 + mf * 16 + q;
            g_denomp[jh * 4 + wx][row] = r0;
            g_denomp[jh * 4 + wx][row + 8] = r1;
        }
    }

    // ---- last CTA computes the final loss ----
    __threadfence();
    __shared__ int amLast;
    if (tid == 0) amLast = (atomicAdd(&g_arrive, 1) == gridDim.x - 1);
    __syncthreads();
    if (amLast) {
        __threadfence();
        float s = 0.0f;
        for (int i = tid; i < N2; i += 512) {
            float den = 0.f;
#pragma unroll
            for (int p = 0; p < 8; ++p) den += g_denomp[p][i];
            s += lg2(den + 1e-7f) * 0.6931471805599453f - 2.0f * g_pos[i];
        }
        float* red = reinterpret_cast<float*>(smem + OFF_B);
        red[tid] = s;
        __syncthreads();
        for (int st = 256; st; st >>= 1) {
            if (tid < st) red[tid] += red[tid + st];
            __syncthreads();
        }
        if (tid == 0) {
            out[0] = red[0] / (float)N2;
            g_arrive = 0;
        }
    }
}

// ---------------------------------------------------------------------------
extern "C" void kernel_launch(void* const* d_in, const int* in_sizes, int n_in,
                              void* d_out, int out_size) {
    const float* emb_i = (const float*)d_in[0];
    const float* emb_j = (const float*)d_in[1];
    const int*   traw  = (const int*)d_in[2];
    float* out = (float*)d_out;

    cudaFuncSetAttribute(simloss_kernel,
                         cudaFuncAttributeMaxDynamicSharedMemorySize, SMEM_TOTAL);

    normpos_kernel<<<BSZ, 128>>>(emb_i, emb_j, traw);
    simloss_kernel<<<128, 512, SMEM_TOTAL>>>(out);
}